// round 2
// baseline (speedup 1.0000x reference)
#include <cuda_runtime.h>
#include <math.h>

#define L_LAYERS 32
#define BEAM 8
#define KV2 2
#define HEADS 8
#define SEQ 1024
#define HDIM 64
#define VOCAB 50257
#define HIST 128
#define TOPK 8

// per-(l,b) slab: KV2*HEADS*SEQ*HDIM floats = 1,048,576 floats = 262,144 float4
#define SLAB_F4 262144
#define NUM_SLABS (L_LAYERS * BEAM)          // 256
#define KV_ELEMS (268435456LL)               // 32*8*2*8*1024*64

// output offsets (float32 elements, concatenated in reference return order)
#define OFF_KV   0LL
#define OFF_SAVE 268435456LL
#define OFF_PROB 268436488LL
#define OFF_TBI  268436496LL
#define OFF_MAX  268436504LL

// device-global scratch (no allocations allowed)
__device__ float g_cand_val[BEAM * TOPK];
__device__ int   g_cand_idx[BEAM * TOPK];
__device__ int   g_beam_index[BEAM];

__device__ __forceinline__ bool cand_gt(float av, int ai, float bv, int bi) {
    // strictly greater value wins; on exact tie, lower index wins (jax.lax.top_k order)
    return (av > bv) || (av == bv && ai < bi);
}

// ---------------------------------------------------------------------------
// Kernel 1: per-row logsumexp + top-8. One block per beam row.
// ---------------------------------------------------------------------------
__global__ void row_topk_kernel(const float* __restrict__ logits,
                                const float* __restrict__ prev_prob) {
    const int r = blockIdx.x;
    const int tid = threadIdx.x;
    const int T = 256;
    const float* row = logits + (long long)r * VOCAB;

    // thread-local sorted (descending) top-8
    float lv[TOPK];
    int   li[TOPK];
#pragma unroll
    for (int j = 0; j < TOPK; j++) { lv[j] = -INFINITY; li[j] = 0x7fffffff; }

    for (int i = tid; i < VOCAB; i += T) {
        float v = row[i];
        if (cand_gt(v, i, lv[TOPK - 1], li[TOPK - 1])) {
            int j = TOPK - 1;
            while (j > 0 && cand_gt(v, i, lv[j - 1], li[j - 1])) {
                lv[j] = lv[j - 1]; li[j] = li[j - 1]; j--;
            }
            lv[j] = v; li[j] = i;
        }
    }

    // block-wide max (lv[0] is each thread's max)
    __shared__ float sred[256];
    sred[tid] = lv[0];
    __syncthreads();
    for (int s = 128; s > 0; s >>= 1) {
        if (tid < s) sred[tid] = fmaxf(sred[tid], sred[tid + s]);
        __syncthreads();
    }
    const float m = sred[0];
    __syncthreads();

    // sum of exp(x - m)
    float acc = 0.0f;
    for (int i = tid; i < VOCAB; i += T) acc += expf(row[i] - m);
    sred[tid] = acc;
    __syncthreads();
    for (int s = 128; s > 0; s >>= 1) {
        if (tid < s) sred[tid] += sred[tid + s];
        __syncthreads();
    }
    const float lse = m + logf(sred[0]);
    __syncthreads();

    // tree-merge 256 sorted 8-lists -> top-8 of the row
    __shared__ float sv[256 * TOPK];
    __shared__ int   si[256 * TOPK];
#pragma unroll
    for (int j = 0; j < TOPK; j++) { sv[tid * TOPK + j] = lv[j]; si[tid * TOPK + j] = li[j]; }
    __syncthreads();

    for (int step = 1; step < 256; step <<= 1) {
        if ((tid & (2 * step - 1)) == 0) {
            float* A  = &sv[tid * TOPK];
            int*   Ai = &si[tid * TOPK];
            float* B  = &sv[(tid + step) * TOPK];
            int*   Bi = &si[(tid + step) * TOPK];
            float mv[TOPK]; int mi[TOPK];
            int pa = 0, pb = 0;
#pragma unroll
            for (int j = 0; j < TOPK; j++) {
                // inside the loop pa<=7 and pb<=7 always (pa+pb == j < 8)
                if (cand_gt(A[pa], Ai[pa], B[pb], Bi[pb])) { mv[j] = A[pa]; mi[j] = Ai[pa]; pa++; }
                else                                        { mv[j] = B[pb]; mi[j] = Bi[pb]; pb++; }
            }
#pragma unroll
            for (int j = 0; j < TOPK; j++) { A[j] = mv[j]; Ai[j] = mi[j]; }
        }
        __syncthreads();
    }

    if (tid < TOPK) {
        g_cand_val[r * TOPK + tid] = sv[tid] - lse + prev_prob[r];
        g_cand_idx[r * TOPK + tid] = si[tid];
    }
}

// ---------------------------------------------------------------------------
// Kernel 2: global top-8 over 64 candidates + small outputs.
// ---------------------------------------------------------------------------
__global__ void select_kernel(const int* __restrict__ save_id,
                              float* __restrict__ out) {
    __shared__ float cv[BEAM * TOPK];
    __shared__ int   ci[BEAM * TOPK];
    __shared__ int   s_beam[BEAM];
    __shared__ int   s_tbi[BEAM];
    __shared__ float s_prob[BEAM];

    const int tid = threadIdx.x;
    if (tid < BEAM * TOPK) { cv[tid] = g_cand_val[tid]; ci[tid] = g_cand_idx[tid]; }
    __syncthreads();

    if (tid == 0) {
        bool used[BEAM * TOPK];
        for (int i = 0; i < BEAM * TOPK; i++) used[i] = false;
        for (int b = 0; b < BEAM; b++) {
            int best = -1;
            for (int i = 0; i < BEAM * TOPK; i++) {
                if (used[i]) continue;
                if (best < 0 || cv[i] > cv[best]) best = i;  // strict > keeps lower flat index on ties
            }
            used[best] = true;
            s_beam[b] = best >> 3;   // flat / top_k
            s_tbi[b]  = ci[best];
            s_prob[b] = cv[best];
            g_beam_index[b] = best >> 3;
        }
    }
    __syncthreads();

    // new_save_id: [8, 129] = gathered save_id concat tbi
    for (int i = tid; i < BEAM * (HIST + 1); i += blockDim.x) {
        int b = i / (HIST + 1);
        int c = i % (HIST + 1);
        int val = (c < HIST) ? save_id[s_beam[b] * HIST + c] : s_tbi[b];
        out[OFF_SAVE + i] = (float)val;
    }
    if (tid < BEAM) {
        out[OFF_PROB + tid] = s_prob[tid];
        out[OFF_TBI + tid]  = (float)s_tbi[tid];
    }
    if (tid == 0) out[OFF_MAX] = (float)s_tbi[0];
}

// ---------------------------------------------------------------------------
// Kernel 3: kv_cache gather along the beam axis. float4 streaming copy.
// Each block handles 1024 float4 (16 KB) fully inside one (l, b) slab.
// grid = NUM_SLABS * (SLAB_F4 / 1024) = 256 * 256 = 65536 blocks, 256 threads.
// ---------------------------------------------------------------------------
__global__ void gather_kernel(const float4* __restrict__ kv,
                              float4* __restrict__ out) {
    __shared__ int bi[BEAM];
    if (threadIdx.x < BEAM) bi[threadIdx.x] = g_beam_index[threadIdx.x];
    __syncthreads();

    const int slab        = blockIdx.x >> 8;       // / 256 blocks per slab
    const int blk_in_slab = blockIdx.x & 255;
    const int b = slab & 7;
    const int l = slab >> 3;

    const long long src_base = (long long)(l * BEAM + bi[b]) * SLAB_F4;
    const long long dst_base = (long long)slab * SLAB_F4;
    const int off = blk_in_slab * 1024 + threadIdx.x;

#pragma unroll
    for (int i = 0; i < 4; i++) {
        out[dst_base + off + i * 256] = kv[src_base + off + i * 256];
    }
}

// ---------------------------------------------------------------------------
extern "C" void kernel_launch(void* const* d_in, const int* in_sizes, int n_in,
                              void* d_out, int out_size) {
    const float* kv_cache  = (const float*)d_in[0];
    const float* logits    = (const float*)d_in[1];
    const int*   save_id   = (const int*)d_in[2];
    const float* prev_prob = (const float*)d_in[3];
    float* out = (float*)d_out;

    row_topk_kernel<<<BEAM, 256>>>(logits, prev_prob);
    select_kernel<<<1, 256>>>(save_id, out);
    gather_kernel<<<NUM_SLABS * (SLAB_F4 / 1024), 256>>>(
        (const float4*)kv_cache, (float4*)(out + OFF_KV));
}